// round 9
// baseline (speedup 1.0000x reference)
#include <cuda_runtime.h>
#include <math.h>

#define T_STEPS 4096
#define BATCH   128
#define IN_DIM  96
#define H_DIM   64
#define OUT_DIM 2

#define CHUNK   64
#define NCHUNK  (T_STEPS / CHUNK)   // 64

typedef unsigned long long ull;

// Scratch
__device__ float g_P[(size_t)T_STEPS * BATCH * H_DIM];   // input currents
__device__ ull   g_M[(size_t)T_STEPS * BATCH];           // spike masks
__device__ ulonglong2 g_S[NCHUNK * BATCH];               // per-chunk (syn_end, mem_end)
__device__ ulonglong2 g_Pref[NCHUNK * BATCH];            // per-chunk initial (S, M)
__device__ float2 g_tab[CHUNK];                          // (b^{j+1}, g_j)

// ---------- packed f32x2 helpers ----------
__device__ __forceinline__ void fma2(ull& d, ull a, ull b) {
    asm("fma.rn.f32x2 %0, %1, %2, %0;" : "+l"(d) : "l"(a), "l"(b));
}
__device__ __forceinline__ ull fma2g(ull a, ull b, ull c) {
    ull d;
    asm("fma.rn.f32x2 %0, %1, %2, %3;" : "=l"(d) : "l"(a), "l"(b), "l"(c));
    return d;
}
__device__ __forceinline__ ull add2(ull a, ull b) {
    ull d;
    asm("add.rn.f32x2 %0, %1, %2;" : "=l"(d) : "l"(a), "l"(b));
    return d;
}
__device__ __forceinline__ ull mul2(ull a, ull b) {
    ull d;
    asm("mul.rn.f32x2 %0, %1, %2;" : "=l"(d) : "l"(a), "l"(b));
    return d;
}
__device__ __forceinline__ ull pack2(float x, float y) {
    ull r;
    asm("mov.b64 %0, {%1, %2};" : "=l"(r) : "f"(x), "f"(y));
    return r;
}
__device__ __forceinline__ float lo32(ull v) { return __uint_as_float((unsigned)v); }
__device__ __forceinline__ float hi32(ull v) { return __uint_as_float((unsigned)(v >> 32)); }

__device__ __forceinline__ unsigned smem_u32(const void* p) {
    unsigned a;
    asm("{ .reg .u64 t; cvta.to.shared.u64 t, %1; cvt.u32.u64 %0, t; }" : "=r"(a) : "l"(p));
    return a;
}
__device__ __forceinline__ ull lds_u64(unsigned a) {
    ull v;
    asm("ld.shared.b64 %0, [%1];" : "=l"(v) : "r"(a));
    return v;
}

// ============================================================
// Kernel 1: P[g] = (g >= BATCH) ? x[g-BATCH,:] @ W_h.T : 0
// CTA tile 64 rows x 64 cols, 64 threads, thread tile 8x8.
// ============================================================
__global__ __launch_bounds__(64) void precompute_inp(const float* __restrict__ x,
                                                     const float* __restrict__ Wh) {
    __shared__ ull xp[48][64];
    __shared__ ull wp[48][64];

    const int tid = threadIdx.x;
    const long long row0 = (long long)blockIdx.x * 64;

    const int fr = tid >> 3;
    const int fq = tid & 7;

#pragma unroll
    for (int rr = 0; rr < 8; rr++) {
        int c = rr * 8 + fr;
        const float4* src = (const float4*)(Wh + (size_t)c * IN_DIM) + fq * 3;
#pragma unroll
        for (int j = 0; j < 3; j++) {
            float4 f = src[j];
            int kk = (fq * 3 + j) * 2;
            *(float2*)&wp[kk][c]     = make_float2(f.x, f.y);
            *(float2*)&wp[kk + 1][c] = make_float2(f.z, f.w);
        }
    }
#pragma unroll
    for (int rr = 0; rr < 8; rr++) {
        int r = rr * 8 + fr;
        long long g = row0 + r;
#pragma unroll
        for (int j = 0; j < 3; j++) {
            float4 f = make_float4(0.f, 0.f, 0.f, 0.f);
            if (g >= BATCH)
                f = ((const float4*)(x + (g - BATCH) * IN_DIM))[fq * 3 + j];
            int kk = (fq * 3 + j) * 2;
            *(float2*)&xp[kk][r]     = make_float2(f.x, f.y);
            *(float2*)&xp[kk + 1][r] = make_float2(f.z, f.w);
        }
    }
    __syncthreads();

    const int r0 = (tid & 7) * 8;
    const int c0 = (tid >> 3) * 8;

    ull acc[8][8];
#pragma unroll
    for (int i = 0; i < 8; i++)
#pragma unroll
        for (int j = 0; j < 8; j++) acc[i][j] = 0ull;

#pragma unroll 2
    for (int kk = 0; kk < 48; kk++) {
        ulonglong2 A[4], B[4];
#pragma unroll
        for (int j = 0; j < 4; j++) {
            A[j] = *(const ulonglong2*)&xp[kk][r0 + 2 * j];
            B[j] = *(const ulonglong2*)&wp[kk][c0 + 2 * j];
        }
#pragma unroll
        for (int ri = 0; ri < 8; ri++) {
            ull av = (ri & 1) ? A[ri >> 1].y : A[ri >> 1].x;
#pragma unroll
            for (int cj = 0; cj < 4; cj++) {
                fma2(acc[ri][2 * cj],     av, B[cj].x);
                fma2(acc[ri][2 * cj + 1], av, B[cj].y);
            }
        }
    }

#pragma unroll
    for (int ri = 0; ri < 8; ri++) {
        float4 o0, o1;
        o0.x = lo32(acc[ri][0]) + hi32(acc[ri][0]);
        o0.y = lo32(acc[ri][1]) + hi32(acc[ri][1]);
        o0.z = lo32(acc[ri][2]) + hi32(acc[ri][2]);
        o0.w = lo32(acc[ri][3]) + hi32(acc[ri][3]);
        o1.x = lo32(acc[ri][4]) + hi32(acc[ri][4]);
        o1.y = lo32(acc[ri][5]) + hi32(acc[ri][5]);
        o1.z = lo32(acc[ri][6]) + hi32(acc[ri][6]);
        o1.w = lo32(acc[ri][7]) + hi32(acc[ri][7]);
        float* dst = g_P + (size_t)(row0 + r0 + ri) * H_DIM + c0;
        *(float4*)dst       = o0;
        *(float4*)(dst + 4) = o1;
    }
}

// ============================================================
// Kernel 2: hidden scan, one warp per batch, 6-bit-group LUT.
// lut[p][v][lane] (p=0..11, v=0..63): sum over set bits i of v
// of V columns j(p,i) for neurons (2*lane, 2*lane+1).
//   p in 0..5  -> pm0 bits 6p..6p+5, neurons j = 12p + 2i
//   p in 6..11 -> pm1 bits 6p'..6p'+5, neurons j = 12p' + 2i + 1
// LUT base aligned to 16KB so lookup addr = SHF + LOP3(and-or).
// ============================================================
__global__ __launch_bounds__(32, 1) void scan_kernel(const float* __restrict__ V,
                                                     float a_h, float b_h) {
    extern __shared__ __align__(16) char smem[];

    const int lane = threadIdx.x;
    const int b    = blockIdx.x;

    const unsigned raw32  = smem_u32(smem);
    const unsigned abase  = (raw32 + 16383u) & ~16383u;   // 16KB-aligned
    char* ab = smem + (abase - raw32);

    // ---- build LUT (each lane builds only its own lane slots) ----
    for (int p = 0; p < 12; p++) {
        char* bpp = ab + p * 16384 + lane * 8;
        *(float2*)bpp = make_float2(0.f, 0.f);
        int pm = (p < 6) ? p : p - 6;
#pragma unroll
        for (int i = 0; i < 6; i++) {
            int l = 6 * pm + i;
            float2 c = make_float2(0.f, 0.f);
            if (l < 32) {
                int j = (p < 6) ? 2 * l : 2 * l + 1;
                c.x = V[(size_t)(2 * lane) * H_DIM + j];
                c.y = V[(size_t)(2 * lane + 1) * H_DIM + j];
            }
            *(float2*)(bpp + (1u << i) * 256) = c;
        }
        for (int v = 3; v < 64; v++) {
            if ((v & (v - 1)) == 0) continue;
            float2 e1 = *(const float2*)(bpp + (v & (v - 1)) * 256);
            float2 e2 = *(const float2*)(bpp + (v & (-v)) * 256);
            *(float2*)(bpp + v * 256) = make_float2(e1.x + e2.x, e1.y + e2.y);
        }
    }
    __syncwarp();

    // per-position base addresses (bits 8..13 clear; lane in bits 3..7)
    unsigned bp[12];
#pragma unroll
    for (int p = 0; p < 12; p++) bp[p] = abase + p * 16384 + lane * 8;

    const float omb_h = 1.f - b_h;
    const ull a_h2 = pack2(a_h, a_h);
    const ull omb2 = pack2(omb_h, omb_h);
    const ull b_h2 = pack2(b_h, b_h);

    ull syn2 = 0ull, mem2 = 0ull;

    const int strideP = BATCH * H_DIM;
    const float* p = g_P + (size_t)b * H_DIM + 2 * lane;
    float2 cur[8];
#pragma unroll
    for (int q = 0; q < 8; q++) cur[q] = *(const float2*)(p + (size_t)q * strideP);
    const float* pf = p + (size_t)8 * strideP;

    ull* mptr = g_M + b;
    unsigned pm0 = 0u, pm1 = 0u;
    const unsigned M6 = 0x3F00u;

    for (int tb = 0; tb < T_STEPS; tb += 8) {
#pragma unroll
        for (int q8 = 0; q8 < 8; q8++) {
            const int t = tb + q8;

            ull h0 = lds_u64(((pm0 << 8)  & M6) | bp[0]);
            ull h1 = lds_u64(((pm0 << 2)  & M6) | bp[1]);
            ull h2 = lds_u64(((pm0 >> 4)  & M6) | bp[2]);
            ull h3 = lds_u64(((pm0 >> 10) & M6) | bp[3]);
            ull h4 = lds_u64(((pm0 >> 16) & M6) | bp[4]);
            ull h5 = lds_u64(((pm0 >> 22) & M6) | bp[5]);
            ull h6 = lds_u64(((pm1 << 8)  & M6) | bp[6]);
            ull h7 = lds_u64(((pm1 << 2)  & M6) | bp[7]);
            ull h8 = lds_u64(((pm1 >> 4)  & M6) | bp[8]);
            ull h9 = lds_u64(((pm1 >> 10) & M6) | bp[9]);
            ull hA = lds_u64(((pm1 >> 16) & M6) | bp[10]);
            ull hB = lds_u64(((pm1 >> 22) & M6) | bp[11]);

            float2 c = cur[q8];
            if (t + 8 < T_STEPS) cur[q8] = *(const float2*)pf;  // register ring prefetch
            pf += strideP;

            ull s01 = add2(h0, h1);
            ull s23 = add2(h2, h3);
            ull s45 = add2(h4, h5);
            ull s67 = add2(h6, h7);
            ull s89 = add2(h8, h9);
            ull sAB = add2(hA, hB);
            ull sA4 = add2(s01, s23);
            ull sB4 = add2(s45, s67);
            ull sC4 = add2(s89, sAB);
            ull sD4 = add2(pack2(c.x, c.y), sA4);
            ull tot = add2(add2(sB4, sC4), sD4);

            syn2 = fma2g(a_h2, syn2, tot);
            mem2 = fma2g(b_h2, mem2, mul2(omb2, syn2));
            float m0 = lo32(mem2), m1 = hi32(mem2);
            bool s0 = (m0 > 1.f);
            bool s1 = (m1 > 1.f);
            m0 = s0 ? 0.f : m0;
            m1 = s1 ? 0.f : m1;
            mem2 = pack2(m0, m1);
            pm0 = __ballot_sync(0xffffffffu, s0);
            pm1 = __ballot_sync(0xffffffffu, s1);

            if (lane == 0)
                mptr[(size_t)t * BATCH] = (ull)pm0 | ((ull)pm1 << 32);
        }
    }
}

// ============================================================
// Kernel 3 (R1): per-chunk local readout scans from masks.
// Grid = NCHUNK CTAs x 128 threads (thread = batch). Writes
// provisional mem_o to out and (syn_end, mem_end) to g_S.
// ============================================================
__global__ __launch_bounds__(128) void readout_chunks(const float* __restrict__ Wo,
                                                      float* __restrict__ out,
                                                      float a_o, float b_o) {
    __shared__ float2 lutOb[8 * 256];  // byte LUT, 16 KB

    const int tid = threadIdx.x;
    const int c   = blockIdx.x;

    for (int idx = tid; idx < 8 * 256; idx += 128) {
        int pp = idx >> 8, v = idx & 255;
        float2 s = make_float2(0.f, 0.f);
#pragma unroll
        for (int i = 0; i < 8; i++) {
            if (v & (1 << i)) {
                int j = (pp < 4) ? 2 * (8 * pp + i) : 2 * (8 * (pp - 4) + i) + 1;
                s.x += Wo[j];
                s.y += Wo[H_DIM + j];
            }
        }
        lutOb[idx] = s;
    }
    __syncthreads();

    const int b = tid;
    const ull a_o2  = pack2(a_o, a_o);
    const ull b_o2  = pack2(b_o, b_o);
    const ull ombo2 = pack2(1.f - b_o, 1.f - b_o);

    ull syno2 = 0ull, memo2 = 0ull;

    // mask ring: need g_M[(c*64 - 1 + j)*B + b]
    const ull* mp = g_M + ((long long)c * CHUNK - 1) * BATCH + b;
    ull ring[8];
#pragma unroll
    for (int q = 0; q < 8; q++)
        ring[q] = (c == 0 && q == 0) ? 0ull : mp[(size_t)q * BATCH];
    const ull* pfm = mp + (size_t)8 * BATCH;

    ull* optr = (ull*)out + (size_t)c * CHUNK * BATCH + b;

    for (int jb = 0; jb < CHUNK; jb += 8) {
#pragma unroll
        for (int q8 = 0; q8 < 8; q8++) {
            const int j = jb + q8;
            ull m = ring[q8];
            if (j + 8 < CHUNK) ring[q8] = *pfm;
            pfm += BATCH;

            unsigned p0 = (unsigned)m, p1 = (unsigned)(m >> 32);
            ull r0 = add2(*(const ull*)&lutOb[0 * 256 + (p0 & 255u)],
                          *(const ull*)&lutOb[4 * 256 + (p1 & 255u)]);
            ull r1 = add2(*(const ull*)&lutOb[1 * 256 + ((p0 >> 8) & 255u)],
                          *(const ull*)&lutOb[5 * 256 + ((p1 >> 8) & 255u)]);
            ull r2 = add2(*(const ull*)&lutOb[2 * 256 + ((p0 >> 16) & 255u)],
                          *(const ull*)&lutOb[6 * 256 + ((p1 >> 16) & 255u)]);
            ull r3 = add2(*(const ull*)&lutOb[3 * 256 + (p0 >> 24)],
                          *(const ull*)&lutOb[7 * 256 + (p1 >> 24)]);
            ull d2 = add2(add2(r0, r1), add2(r2, r3));

            syno2 = fma2g(a_o2, syno2, d2);
            memo2 = fma2g(b_o2, memo2, mul2(ombo2, syno2));
            optr[(size_t)j * BATCH] = memo2;
        }
    }
    g_S[c * BATCH + b] = make_ulonglong2(syno2, memo2);
}

// ============================================================
// Kernel 4 (R2): chunk prefix + fixup tables. 1 CTA x 128 thr.
// ============================================================
__global__ __launch_bounds__(128) void readout_prefix(float a_o, float b_o) {
    const int b = threadIdx.x;

    // tables: tab[j] = (b^{j+1}, g_j), g_j = b*g_{j-1} + (1-b)*a^{j+1}
    float ap = a_o, bpw = b_o, g = (1.f - b_o) * a_o;
    float a64 = 0.f, b64 = 0.f, g63 = 0.f;
    for (int j = 0; j < CHUNK; j++) {
        if (b == 0) g_tab[j] = make_float2(bpw, g);
        if (j == CHUNK - 1) { a64 = ap; b64 = bpw; g63 = g; }
        ap *= a_o;
        bpw *= b_o;
        g = b_o * g + (1.f - b_o) * ap;
    }

    const ull a64_2 = pack2(a64, a64);
    const ull b64_2 = pack2(b64, b64);
    const ull g63_2 = pack2(g63, g63);

    ull S = 0ull, M = 0ull;
    for (int c = 0; c < NCHUNK; c++) {
        g_Pref[c * BATCH + b] = make_ulonglong2(S, M);
        ulonglong2 sm = g_S[c * BATCH + b];
        ull Sold = S;
        S = fma2g(a64_2, S, sm.x);
        M = add2(fma2g(b64_2, M, sm.y), mul2(g63_2, Sold));
    }
}

// ============================================================
// Kernel 5 (R3): fixup: out[t][b] += b^{j+1}*M_c + g_j*S_c
// ============================================================
__global__ __launch_bounds__(256) void readout_fix(float* __restrict__ out) {
    const size_t idx = (size_t)blockIdx.x * 256 + threadIdx.x;  // t*BATCH + b
    const int t = (int)(idx >> 7);
    const int b = (int)(idx & 127);
    const int c = t >> 6;
    const int j = t & 63;

    float2 tab = g_tab[j];
    ulonglong2 pref = g_Pref[c * BATCH + b];
    ull fix = add2(mul2(pack2(tab.x, tab.x), pref.y),
                   mul2(pack2(tab.y, tab.y), pref.x));
    ull* o = (ull*)out + idx;
    *o = add2(*o, fix);
}

// ============================================================
extern "C" void kernel_launch(void* const* d_in, const int* in_sizes, int n_in,
                              void* d_out, int out_size) {
    const float* x  = (const float*)d_in[0];
    const float* Wh = (const float*)d_in[1];
    const float* V  = (const float*)d_in[2];
    const float* Wo = (const float*)d_in[3];
    float* out = (float*)d_out;

    const double S = log1p(exp(1.0));
    const float a_h = expf((float)(-0.004 / (S * 0.01)));
    const float b_h = expf((float)(-0.004 / (S * 0.02)));

    const int smem_scan = 12 * 16384 + 16384;  // 208 KB (incl. alignment pad)
    cudaFuncSetAttribute(scan_kernel, cudaFuncAttributeMaxDynamicSharedMemorySize,
                         smem_scan);

    precompute_inp<<<(T_STEPS * BATCH) / 64, 64>>>(x, Wh);
    scan_kernel<<<BATCH, 32, smem_scan>>>(V, a_h, b_h);
    readout_chunks<<<NCHUNK, 128>>>(Wo, out, a_h, b_h);
    readout_prefix<<<1, 128>>>(a_h, b_h);
    readout_fix<<<(T_STEPS * BATCH) / 256, 256>>>(out);
}

// round 10
// speedup vs baseline: 1.0019x; 1.0019x over previous
#include <cuda_runtime.h>
#include <math.h>

#define T_STEPS 4096
#define BATCH   128
#define IN_DIM  96
#define H_DIM   64
#define OUT_DIM 2

#define CHUNK   64
#define NCHUNK  (T_STEPS / CHUNK)   // 64

typedef unsigned long long ull;

// Scratch
__device__ float g_P[(size_t)T_STEPS * BATCH * H_DIM];   // input currents
__device__ ull   g_M[(size_t)T_STEPS * BATCH];           // spike masks
__device__ ulonglong2 g_S[NCHUNK * BATCH];               // per-chunk (syn_end, mem_end)
__device__ ulonglong2 g_Pref[NCHUNK * BATCH];            // per-chunk initial (S, M)
__device__ float2 g_tab[CHUNK];                          // (b^{j+1}, g_j)

// ---------- packed f32x2 helpers ----------
__device__ __forceinline__ void fma2(ull& d, ull a, ull b) {
    asm("fma.rn.f32x2 %0, %1, %2, %0;" : "+l"(d) : "l"(a), "l"(b));
}
__device__ __forceinline__ ull fma2g(ull a, ull b, ull c) {
    ull d;
    asm("fma.rn.f32x2 %0, %1, %2, %3;" : "=l"(d) : "l"(a), "l"(b), "l"(c));
    return d;
}
__device__ __forceinline__ ull add2(ull a, ull b) {
    ull d;
    asm("add.rn.f32x2 %0, %1, %2;" : "=l"(d) : "l"(a), "l"(b));
    return d;
}
__device__ __forceinline__ ull mul2(ull a, ull b) {
    ull d;
    asm("mul.rn.f32x2 %0, %1, %2;" : "=l"(d) : "l"(a), "l"(b));
    return d;
}
__device__ __forceinline__ ull pack2(float x, float y) {
    ull r;
    asm("mov.b64 %0, {%1, %2};" : "=l"(r) : "f"(x), "f"(y));
    return r;
}
__device__ __forceinline__ float lo32(ull v) { return __uint_as_float((unsigned)v); }
__device__ __forceinline__ float hi32(ull v) { return __uint_as_float((unsigned)(v >> 32)); }

__device__ __forceinline__ unsigned smem_u32(const void* p) {
    unsigned a;
    asm("{ .reg .u64 t; cvta.to.shared.u64 t, %1; cvt.u32.u64 %0, t; }" : "=r"(a) : "l"(p));
    return a;
}
__device__ __forceinline__ ull lds_u64(unsigned a) {
    ull v;
    asm("ld.shared.b64 %0, [%1];" : "=l"(v) : "r"(a));
    return v;
}

// ============================================================
// Kernel 1: P[g] = (g >= BATCH) ? x[g-BATCH,:] @ W_h.T : 0
// CTA tile 64 rows x 64 cols, 64 threads, thread tile 8x8.
// ============================================================
__global__ __launch_bounds__(64) void precompute_inp(const float* __restrict__ x,
                                                     const float* __restrict__ Wh) {
    __shared__ ull xp[48][64];
    __shared__ ull wp[48][64];

    const int tid = threadIdx.x;
    const long long row0 = (long long)blockIdx.x * 64;

    const int fr = tid >> 3;
    const int fq = tid & 7;

#pragma unroll
    for (int rr = 0; rr < 8; rr++) {
        int c = rr * 8 + fr;
        const float4* src = (const float4*)(Wh + (size_t)c * IN_DIM) + fq * 3;
#pragma unroll
        for (int j = 0; j < 3; j++) {
            float4 f = src[j];
            int kk = (fq * 3 + j) * 2;
            *(float2*)&wp[kk][c]     = make_float2(f.x, f.y);
            *(float2*)&wp[kk + 1][c] = make_float2(f.z, f.w);
        }
    }
#pragma unroll
    for (int rr = 0; rr < 8; rr++) {
        int r = rr * 8 + fr;
        long long g = row0 + r;
#pragma unroll
        for (int j = 0; j < 3; j++) {
            float4 f = make_float4(0.f, 0.f, 0.f, 0.f);
            if (g >= BATCH)
                f = ((const float4*)(x + (g - BATCH) * IN_DIM))[fq * 3 + j];
            int kk = (fq * 3 + j) * 2;
            *(float2*)&xp[kk][r]     = make_float2(f.x, f.y);
            *(float2*)&xp[kk + 1][r] = make_float2(f.z, f.w);
        }
    }
    __syncthreads();

    const int r0 = (tid & 7) * 8;
    const int c0 = (tid >> 3) * 8;

    ull acc[8][8];
#pragma unroll
    for (int i = 0; i < 8; i++)
#pragma unroll
        for (int j = 0; j < 8; j++) acc[i][j] = 0ull;

#pragma unroll 2
    for (int kk = 0; kk < 48; kk++) {
        ulonglong2 A[4], B[4];
#pragma unroll
        for (int j = 0; j < 4; j++) {
            A[j] = *(const ulonglong2*)&xp[kk][r0 + 2 * j];
            B[j] = *(const ulonglong2*)&wp[kk][c0 + 2 * j];
        }
#pragma unroll
        for (int ri = 0; ri < 8; ri++) {
            ull av = (ri & 1) ? A[ri >> 1].y : A[ri >> 1].x;
#pragma unroll
            for (int cj = 0; cj < 4; cj++) {
                fma2(acc[ri][2 * cj],     av, B[cj].x);
                fma2(acc[ri][2 * cj + 1], av, B[cj].y);
            }
        }
    }

#pragma unroll
    for (int ri = 0; ri < 8; ri++) {
        float4 o0, o1;
        o0.x = lo32(acc[ri][0]) + hi32(acc[ri][0]);
        o0.y = lo32(acc[ri][1]) + hi32(acc[ri][1]);
        o0.z = lo32(acc[ri][2]) + hi32(acc[ri][2]);
        o0.w = lo32(acc[ri][3]) + hi32(acc[ri][3]);
        o1.x = lo32(acc[ri][4]) + hi32(acc[ri][4]);
        o1.y = lo32(acc[ri][5]) + hi32(acc[ri][5]);
        o1.z = lo32(acc[ri][6]) + hi32(acc[ri][6]);
        o1.w = lo32(acc[ri][7]) + hi32(acc[ri][7]);
        float* dst = g_P + (size_t)(row0 + r0 + ri) * H_DIM + c0;
        *(float4*)dst       = o0;
        *(float4*)(dst + 4) = o1;
    }
}

// ============================================================
// Kernel 2: hidden scan, one warp per batch, 6-bit-group LUT.
// lut[p][v][lane] (p=0..11, v=0..63): sum over set bits i of v
// of V columns j(p,i) for neurons (2*lane, 2*lane+1).
//   p in 0..5  -> pm0 bits 6p..6p+5, neurons j = 12p + 2i
//   p in 6..11 -> pm1 bits 6p'..6p'+5, neurons j = 12p' + 2i + 1
// LUT base aligned to 16KB so lookup addr = SHF + LOP3(and-or).
// ============================================================
__global__ __launch_bounds__(32, 1) void scan_kernel(const float* __restrict__ V,
                                                     float a_h, float b_h) {
    extern __shared__ __align__(16) char smem[];

    const int lane = threadIdx.x;
    const int b    = blockIdx.x;

    const unsigned raw32  = smem_u32(smem);
    const unsigned abase  = (raw32 + 16383u) & ~16383u;   // 16KB-aligned
    char* ab = smem + (abase - raw32);

    // ---- build LUT (each lane builds only its own lane slots) ----
    for (int p = 0; p < 12; p++) {
        char* bpp = ab + p * 16384 + lane * 8;
        *(float2*)bpp = make_float2(0.f, 0.f);
        int pm = (p < 6) ? p : p - 6;
#pragma unroll
        for (int i = 0; i < 6; i++) {
            int l = 6 * pm + i;
            float2 c = make_float2(0.f, 0.f);
            if (l < 32) {
                int j = (p < 6) ? 2 * l : 2 * l + 1;
                c.x = V[(size_t)(2 * lane) * H_DIM + j];
                c.y = V[(size_t)(2 * lane + 1) * H_DIM + j];
            }
            *(float2*)(bpp + (1u << i) * 256) = c;
        }
        for (int v = 3; v < 64; v++) {
            if ((v & (v - 1)) == 0) continue;
            float2 e1 = *(const float2*)(bpp + (v & (v - 1)) * 256);
            float2 e2 = *(const float2*)(bpp + (v & (-v)) * 256);
            *(float2*)(bpp + v * 256) = make_float2(e1.x + e2.x, e1.y + e2.y);
        }
    }
    __syncwarp();

    // per-position base addresses (bits 8..13 clear; lane in bits 3..7)
    unsigned bp[12];
#pragma unroll
    for (int p = 0; p < 12; p++) bp[p] = abase + p * 16384 + lane * 8;

    const float omb_h = 1.f - b_h;
    const ull a_h2 = pack2(a_h, a_h);
    const ull omb2 = pack2(omb_h, omb_h);
    const ull b_h2 = pack2(b_h, b_h);

    ull syn2 = 0ull, mem2 = 0ull;

    const int strideP = BATCH * H_DIM;
    const float* p = g_P + (size_t)b * H_DIM + 2 * lane;
    float2 cur[8];
#pragma unroll
    for (int q = 0; q < 8; q++) cur[q] = *(const float2*)(p + (size_t)q * strideP);
    const float* pf = p + (size_t)8 * strideP;

    ull* mptr = g_M + b;
    unsigned pm0 = 0u, pm1 = 0u;
    const unsigned M6 = 0x3F00u;

    for (int tb = 0; tb < T_STEPS; tb += 8) {
#pragma unroll
        for (int q8 = 0; q8 < 8; q8++) {
            const int t = tb + q8;

            ull h0 = lds_u64(((pm0 << 8)  & M6) | bp[0]);
            ull h1 = lds_u64(((pm0 << 2)  & M6) | bp[1]);
            ull h2 = lds_u64(((pm0 >> 4)  & M6) | bp[2]);
            ull h3 = lds_u64(((pm0 >> 10) & M6) | bp[3]);
            ull h4 = lds_u64(((pm0 >> 16) & M6) | bp[4]);
            ull h5 = lds_u64(((pm0 >> 22) & M6) | bp[5]);
            ull h6 = lds_u64(((pm1 << 8)  & M6) | bp[6]);
            ull h7 = lds_u64(((pm1 << 2)  & M6) | bp[7]);
            ull h8 = lds_u64(((pm1 >> 4)  & M6) | bp[8]);
            ull h9 = lds_u64(((pm1 >> 10) & M6) | bp[9]);
            ull hA = lds_u64(((pm1 >> 16) & M6) | bp[10]);
            ull hB = lds_u64(((pm1 >> 22) & M6) | bp[11]);

            float2 c = cur[q8];
            if (t + 8 < T_STEPS) cur[q8] = *(const float2*)pf;  // register ring prefetch
            pf += strideP;

            ull s01 = add2(h0, h1);
            ull s23 = add2(h2, h3);
            ull s45 = add2(h4, h5);
            ull s67 = add2(h6, h7);
            ull s89 = add2(h8, h9);
            ull sAB = add2(hA, hB);
            ull sA4 = add2(s01, s23);
            ull sB4 = add2(s45, s67);
            ull sC4 = add2(s89, sAB);
            ull sD4 = add2(pack2(c.x, c.y), sA4);
            ull tot = add2(add2(sB4, sC4), sD4);

            syn2 = fma2g(a_h2, syn2, tot);
            mem2 = fma2g(b_h2, mem2, mul2(omb2, syn2));
            float m0 = lo32(mem2), m1 = hi32(mem2);
            bool s0 = (m0 > 1.f);
            bool s1 = (m1 > 1.f);
            m0 = s0 ? 0.f : m0;
            m1 = s1 ? 0.f : m1;
            mem2 = pack2(m0, m1);
            pm0 = __ballot_sync(0xffffffffu, s0);
            pm1 = __ballot_sync(0xffffffffu, s1);

            if (lane == 0)
                mptr[(size_t)t * BATCH] = (ull)pm0 | ((ull)pm1 << 32);
        }
    }
}

// ============================================================
// Kernel 3 (R1): per-chunk local readout scans from masks.
// Grid = NCHUNK CTAs x 128 threads (thread = batch). Writes
// provisional mem_o to out and (syn_end, mem_end) to g_S.
// ============================================================
__global__ __launch_bounds__(128) void readout_chunks(const float* __restrict__ Wo,
                                                      float* __restrict__ out,
                                                      float a_o, float b_o) {
    __shared__ float2 lutOb[8 * 256];  // byte LUT, 16 KB

    const int tid = threadIdx.x;
    const int c   = blockIdx.x;

    for (int idx = tid; idx < 8 * 256; idx += 128) {
        int pp = idx >> 8, v = idx & 255;
        float2 s = make_float2(0.f, 0.f);
#pragma unroll
        for (int i = 0; i < 8; i++) {
            if (v & (1 << i)) {
                int j = (pp < 4) ? 2 * (8 * pp + i) : 2 * (8 * (pp - 4) + i) + 1;
                s.x += Wo[j];
                s.y += Wo[H_DIM + j];
            }
        }
        lutOb[idx] = s;
    }
    __syncthreads();

    const int b = tid;
    const ull a_o2  = pack2(a_o, a_o);
    const ull b_o2  = pack2(b_o, b_o);
    const ull ombo2 = pack2(1.f - b_o, 1.f - b_o);

    ull syno2 = 0ull, memo2 = 0ull;

    // mask ring: need g_M[(c*64 - 1 + j)*B + b]
    const ull* mp = g_M + ((long long)c * CHUNK - 1) * BATCH + b;
    ull ring[8];
#pragma unroll
    for (int q = 0; q < 8; q++)
        ring[q] = (c == 0 && q == 0) ? 0ull : mp[(size_t)q * BATCH];
    const ull* pfm = mp + (size_t)8 * BATCH;

    ull* optr = (ull*)out + (size_t)c * CHUNK * BATCH + b;

    for (int jb = 0; jb < CHUNK; jb += 8) {
#pragma unroll
        for (int q8 = 0; q8 < 8; q8++) {
            const int j = jb + q8;
            ull m = ring[q8];
            if (j + 8 < CHUNK) ring[q8] = *pfm;
            pfm += BATCH;

            unsigned p0 = (unsigned)m, p1 = (unsigned)(m >> 32);
            ull r0 = add2(*(const ull*)&lutOb[0 * 256 + (p0 & 255u)],
                          *(const ull*)&lutOb[4 * 256 + (p1 & 255u)]);
            ull r1 = add2(*(const ull*)&lutOb[1 * 256 + ((p0 >> 8) & 255u)],
                          *(const ull*)&lutOb[5 * 256 + ((p1 >> 8) & 255u)]);
            ull r2 = add2(*(const ull*)&lutOb[2 * 256 + ((p0 >> 16) & 255u)],
                          *(const ull*)&lutOb[6 * 256 + ((p1 >> 16) & 255u)]);
            ull r3 = add2(*(const ull*)&lutOb[3 * 256 + (p0 >> 24)],
                          *(const ull*)&lutOb[7 * 256 + (p1 >> 24)]);
            ull d2 = add2(add2(r0, r1), add2(r2, r3));

            syno2 = fma2g(a_o2, syno2, d2);
            memo2 = fma2g(b_o2, memo2, mul2(ombo2, syno2));
            optr[(size_t)j * BATCH] = memo2;
        }
    }
    g_S[c * BATCH + b] = make_ulonglong2(syno2, memo2);
}

// ============================================================
// Kernel 4 (R2): chunk prefix + fixup tables. 1 CTA x 128 thr.
// ============================================================
__global__ __launch_bounds__(128) void readout_prefix(float a_o, float b_o) {
    const int b = threadIdx.x;

    // tables: tab[j] = (b^{j+1}, g_j), g_j = b*g_{j-1} + (1-b)*a^{j+1}
    float ap = a_o, bpw = b_o, g = (1.f - b_o) * a_o;
    float a64 = 0.f, b64 = 0.f, g63 = 0.f;
    for (int j = 0; j < CHUNK; j++) {
        if (b == 0) g_tab[j] = make_float2(bpw, g);
        if (j == CHUNK - 1) { a64 = ap; b64 = bpw; g63 = g; }
        ap *= a_o;
        bpw *= b_o;
        g = b_o * g + (1.f - b_o) * ap;
    }

    const ull a64_2 = pack2(a64, a64);
    const ull b64_2 = pack2(b64, b64);
    const ull g63_2 = pack2(g63, g63);

    ull S = 0ull, M = 0ull;
    for (int c = 0; c < NCHUNK; c++) {
        g_Pref[c * BATCH + b] = make_ulonglong2(S, M);
        ulonglong2 sm = g_S[c * BATCH + b];
        ull Sold = S;
        S = fma2g(a64_2, S, sm.x);
        M = add2(fma2g(b64_2, M, sm.y), mul2(g63_2, Sold));
    }
}

// ============================================================
// Kernel 5 (R3): fixup: out[t][b] += b^{j+1}*M_c + g_j*S_c
// ============================================================
__global__ __launch_bounds__(256) void readout_fix(float* __restrict__ out) {
    const size_t idx = (size_t)blockIdx.x * 256 + threadIdx.x;  // t*BATCH + b
    const int t = (int)(idx >> 7);
    const int b = (int)(idx & 127);
    const int c = t >> 6;
    const int j = t & 63;

    float2 tab = g_tab[j];
    ulonglong2 pref = g_Pref[c * BATCH + b];
    ull fix = add2(mul2(pack2(tab.x, tab.x), pref.y),
                   mul2(pack2(tab.y, tab.y), pref.x));
    ull* o = (ull*)out + idx;
    *o = add2(*o, fix);
}

// ============================================================
extern "C" void kernel_launch(void* const* d_in, const int* in_sizes, int n_in,
                              void* d_out, int out_size) {
    const float* x  = (const float*)d_in[0];
    const float* Wh = (const float*)d_in[1];
    const float* V  = (const float*)d_in[2];
    const float* Wo = (const float*)d_in[3];
    float* out = (float*)d_out;

    const double S = log1p(exp(1.0));
    const float a_h = expf((float)(-0.004 / (S * 0.01)));
    const float b_h = expf((float)(-0.004 / (S * 0.02)));

    const int smem_scan = 12 * 16384 + 16384;  // 208 KB (incl. alignment pad)
    cudaFuncSetAttribute(scan_kernel, cudaFuncAttributeMaxDynamicSharedMemorySize,
                         smem_scan);

    precompute_inp<<<(T_STEPS * BATCH) / 64, 64>>>(x, Wh);
    scan_kernel<<<BATCH, 32, smem_scan>>>(V, a_h, b_h);
    readout_chunks<<<NCHUNK, 128>>>(Wo, out, a_h, b_h);
    readout_prefix<<<1, 128>>>(a_h, b_h);
    readout_fix<<<(T_STEPS * BATCH) / 256, 256>>>(out);
}